// round 1
// baseline (speedup 1.0000x reference)
#include <cuda_runtime.h>

static constexpr int N_   = 20000;
static constexpr int E_   = 320000;
static constexpr int M_   = 3;
static constexpr int IN_  = 128;
static constexpr int H_   = 4;
static constexpr int D_   = 64;
static constexpr int HD_  = 256;   // H*D
static constexpr int HID_ = 128;

// ---------------- scratch (device globals; no runtime allocation) ----------------
__device__ float g_feat[(size_t)M_ * N_ * HD_];   // 61.4 MB  feat = h @ W[m]
__device__ float g_z   [(size_t)M_ * N_ * HD_];   // 61.4 MB  per-metapath GAT out
__device__ float g_el  [(size_t)M_ * N_ * H_];
__device__ float g_er  [(size_t)M_ * N_ * H_];
__device__ int   g_deg [M_ * N_];
__device__ int   g_off [M_ * (N_ + 1)];
__device__ int   g_cur [M_ * N_];
__device__ int   g_srcs[M_ * E_];
__device__ float g_hid [(size_t)M_ * N_ * HID_];  // 30.7 MB  tanh(z@W1+b1)
__device__ float g_wsum[M_];
__device__ float g_beta[M_];

// ---------------- packed fp32x2 FMA (Blackwell; 2x fp32 FMA throughput) ----------
#define PACK2(d, lo, hi)  asm("mov.b64 %0, {%1, %2};" : "=l"(d) : "r"(lo), "r"(hi))
#define UNPACK2(lo, hi, s) asm("mov.b64 {%0, %1}, %2;" : "=r"(lo), "=r"(hi) : "l"(s))
#define FMA2(d, a, b, c)  asm("fma.rn.f32x2 %0, %1, %2, %3;" : "=l"(d) : "l"(a), "l"(b), "l"(c))

__device__ __forceinline__ float lrelu(float x) { return x > 0.f ? x : 0.2f * x; }

// ---------------- init: zero histogram + wsum ----------------
__global__ void init_kernel() {
    int i = blockIdx.x * blockDim.x + threadIdx.x;
    if (i < M_ * N_) g_deg[i] = 0;
    if (i < M_)      g_wsum[i] = 0.f;
}

// ---------------- tiled GEMM: C[row,col] = sum_k A[row,k]*B[k,col] ----------------
// BM=64, BN=64, BK=16, 256 threads, 4x4 per thread, f32x2 packed FMA inner loop.
__global__ __launch_bounds__(256) void gemm_kernel(
    const float* __restrict__ A, const float* __restrict__ B, float* __restrict__ C,
    int Mrows, int K, int Ncols,
    long aStride, long bStride, long cStride,
    const float* __restrict__ bias, int doTanh)
{
    constexpr int BM = 64, BN = 64, BK = 16;
    __shared__ float As[BK][BM + 4];
    __shared__ float Bs[BK][BN];
    int bz = blockIdx.z;
    A += (long)bz * aStride; B += (long)bz * bStride; C += (long)bz * cStride;

    int tid = threadIdx.x;
    int tx = tid & 15, ty = tid >> 4;
    int rowBase = blockIdx.x * BM, colBase = blockIdx.y * BN;

    unsigned long long acc[4][2];
#pragma unroll
    for (int i = 0; i < 4; i++) { acc[i][0] = 0ull; acc[i][1] = 0ull; }

    int ar = tid >> 2,  ac = (tid & 3)  << 2;   // A tile load: 64 rows x 16 k
    int br = tid >> 4,  bc = (tid & 15) << 2;   // B tile load: 16 k x 64 cols

    for (int k0 = 0; k0 < K; k0 += BK) {
        float4 a4 = make_float4(0.f, 0.f, 0.f, 0.f);
        if (rowBase + ar < Mrows)
            a4 = *(const float4*)(A + (long)(rowBase + ar) * K + (k0 + ac));
        As[ac + 0][ar] = a4.x; As[ac + 1][ar] = a4.y;
        As[ac + 2][ar] = a4.z; As[ac + 3][ar] = a4.w;
        float4 b4 = *(const float4*)(B + (long)(k0 + br) * Ncols + (colBase + bc));
        *(float4*)&Bs[br][bc] = b4;
        __syncthreads();
#pragma unroll
        for (int k = 0; k < BK; k++) {
            float4 ra = *(const float4*)&As[k][ty << 2];
            float4 rb = *(const float4*)&Bs[k][tx << 2];
            unsigned long long b01, b23;
            PACK2(b01, __float_as_uint(rb.x), __float_as_uint(rb.y));
            PACK2(b23, __float_as_uint(rb.z), __float_as_uint(rb.w));
            float rav[4] = {ra.x, ra.y, ra.z, ra.w};
#pragma unroll
            for (int i = 0; i < 4; i++) {
                unsigned long long a2;
                unsigned int au = __float_as_uint(rav[i]);
                PACK2(a2, au, au);
                FMA2(acc[i][0], a2, b01, acc[i][0]);
                FMA2(acc[i][1], a2, b23, acc[i][1]);
            }
        }
        __syncthreads();
    }

#pragma unroll
    for (int i = 0; i < 4; i++) {
        int row = rowBase + (ty << 2) + i;
        if (row >= Mrows) continue;
        int col = colBase + (tx << 2);
        float v[4];
        unsigned int u0, u1;
        UNPACK2(u0, u1, acc[i][0]); v[0] = __uint_as_float(u0); v[1] = __uint_as_float(u1);
        UNPACK2(u0, u1, acc[i][1]); v[2] = __uint_as_float(u0); v[3] = __uint_as_float(u1);
        if (bias) {
            v[0] += bias[col]; v[1] += bias[col + 1];
            v[2] += bias[col + 2]; v[3] += bias[col + 3];
        }
        if (doTanh) {
#pragma unroll
            for (int j = 0; j < 4; j++) v[j] = tanhf(v[j]);
        }
        *(float4*)(C + (long)row * Ncols + col) = make_float4(v[0], v[1], v[2], v[3]);
    }
}

// ---------------- el/er: per-node attention logit halves ----------------
__global__ void elr_kernel(const float* __restrict__ attn_l,
                           const float* __restrict__ attn_r) {
    int g = blockIdx.x * blockDim.x + threadIdx.x;
    int warp = g >> 5, lane = g & 31;
    if (warp >= M_ * N_) return;
    int m = warp / N_;
    const float* frow = g_feat + (size_t)warp * HD_;
    const float* al = attn_l + m * HD_;
    const float* ar = attn_r + m * HD_;
    float el[4] = {0, 0, 0, 0}, er[4] = {0, 0, 0, 0};
#pragma unroll
    for (int k = 0; k < 8; k++) {
        int c = lane + (k << 5);
        float f = frow[c];
        el[k >> 1] += f * al[c];
        er[k >> 1] += f * ar[c];
    }
#pragma unroll
    for (int h = 0; h < 4; h++) {
#pragma unroll
        for (int s = 16; s > 0; s >>= 1) {
            el[h] += __shfl_xor_sync(0xffffffffu, el[h], s);
            er[h] += __shfl_xor_sync(0xffffffffu, er[h], s);
        }
    }
    if (lane == 0) {
        *(float4*)&g_el[(size_t)warp * 4] = make_float4(el[0], el[1], el[2], el[3]);
        *(float4*)&g_er[(size_t)warp * 4] = make_float4(er[0], er[1], er[2], er[3]);
    }
}

// ---------------- CSR build: histogram -> scan -> scatter ----------------
__global__ void hist_kernel(const int* __restrict__ dst) {
    int i = blockIdx.x * blockDim.x + threadIdx.x;
    if (i >= M_ * E_) return;
    int m = i / E_;
    atomicAdd(&g_deg[m * N_ + dst[i]], 1);
}

__global__ void scan_kernel() {
    int m = blockIdx.x;
    __shared__ int sh[256];
    __shared__ int carry;
    int t = threadIdx.x;
    if (t == 0) { carry = 0; g_off[m * (N_ + 1)] = 0; }
    __syncthreads();
    for (int base = 0; base < N_; base += 256) {
        int i = base + t;
        int v = (i < N_) ? g_deg[m * N_ + i] : 0;
        sh[t] = v;
        __syncthreads();
#pragma unroll
        for (int s = 1; s < 256; s <<= 1) {
            int y = (t >= s) ? sh[t - s] : 0;
            __syncthreads();
            sh[t] += y;
            __syncthreads();
        }
        int incl = sh[t];
        int c = carry;
        __syncthreads();
        if (i < N_) {
            g_off[m * (N_ + 1) + i + 1] = c + incl;
            g_cur[m * N_ + i] = c + incl - v;
        }
        if (t == 255) carry = c + sh[255];
        __syncthreads();
    }
}

__global__ void scatter_kernel(const int* __restrict__ src,
                               const int* __restrict__ dst) {
    int i = blockIdx.x * blockDim.x + threadIdx.x;
    if (i >= M_ * E_) return;
    int m = i / E_;
    int d = dst[i];
    int pos = atomicAdd(&g_cur[m * N_ + d], 1);
    g_srcs[m * E_ + pos] = src[i];
}

// ---------------- GAT aggregate: one warp per (metapath, dst node) ----------------
__global__ __launch_bounds__(256) void agg_kernel(const float* __restrict__ bias) {
    int g = blockIdx.x * blockDim.x + threadIdx.x;
    int warp = g >> 5, lane = g & 31;
    if (warp >= M_ * N_) return;
    int m = warp / N_;
    int n = warp - m * N_;
    int start = g_off[m * (N_ + 1) + n];
    int end   = g_off[m * (N_ + 1) + n + 1];

    float4 erd = *(const float4*)&g_er[(size_t)warp * 4];
    const int*   sl  = g_srcs + m * E_;
    const float* elb = g_el  + (size_t)m * N_ * 4;
    const float* fb  = g_feat + (size_t)m * N_ * HD_;

    // phase 1: per-head max (lane-per-edge)
    float mx0 = -1e30f, mx1 = -1e30f, mx2 = -1e30f, mx3 = -1e30f;
    for (int i = start + lane; i < end; i += 32) {
        float4 e4 = *(const float4*)&elb[sl[i] * 4];
        mx0 = fmaxf(mx0, lrelu(e4.x + erd.x));
        mx1 = fmaxf(mx1, lrelu(e4.y + erd.y));
        mx2 = fmaxf(mx2, lrelu(e4.z + erd.z));
        mx3 = fmaxf(mx3, lrelu(e4.w + erd.w));
    }
#pragma unroll
    for (int s = 16; s > 0; s >>= 1) {
        mx0 = fmaxf(mx0, __shfl_xor_sync(0xffffffffu, mx0, s));
        mx1 = fmaxf(mx1, __shfl_xor_sync(0xffffffffu, mx1, s));
        mx2 = fmaxf(mx2, __shfl_xor_sync(0xffffffffu, mx2, s));
        mx3 = fmaxf(mx3, __shfl_xor_sync(0xffffffffu, mx3, s));
    }

    // phase 2: per-head sum of exp
    float s0 = 0, s1 = 0, s2 = 0, s3 = 0;
    for (int i = start + lane; i < end; i += 32) {
        float4 e4 = *(const float4*)&elb[sl[i] * 4];
        s0 += expf(lrelu(e4.x + erd.x) - mx0);
        s1 += expf(lrelu(e4.y + erd.y) - mx1);
        s2 += expf(lrelu(e4.z + erd.z) - mx2);
        s3 += expf(lrelu(e4.w + erd.w) - mx3);
    }
#pragma unroll
    for (int s = 16; s > 0; s >>= 1) {
        s0 += __shfl_xor_sync(0xffffffffu, s0, s);
        s1 += __shfl_xor_sync(0xffffffffu, s1, s);
        s2 += __shfl_xor_sync(0xffffffffu, s2, s);
        s3 += __shfl_xor_sync(0xffffffffu, s3, s);
    }
    float r0 = 1.f / fmaxf(s0, 1e-9f);
    float r1 = 1.f / fmaxf(s1, 1e-9f);
    float r2 = 1.f / fmaxf(s2, 1e-9f);
    float r3 = 1.f / fmaxf(s3, 1e-9f);

    // per-lane head + precomputed selects: lane covers cols [lane*8, lane*8+8)
    int hsel = lane >> 3;
    float er_s = hsel == 0 ? erd.x : hsel == 1 ? erd.y : hsel == 2 ? erd.z : erd.w;
    float mx_s = hsel == 0 ? mx0   : hsel == 1 ? mx1   : hsel == 2 ? mx2   : mx3;
    float r_s  = hsel == 0 ? r0    : hsel == 1 ? r1    : hsel == 2 ? r2    : r3;

    // phase 3: weighted aggregation (warp-cooperative per edge, coalesced float4)
    float4 accA = make_float4(0.f, 0.f, 0.f, 0.f);
    float4 accB = make_float4(0.f, 0.f, 0.f, 0.f);
    for (int i = start; i < end; i++) {
        int s = sl[i];
        float4 e4 = *(const float4*)&elb[s * 4];
        float el_s = hsel == 0 ? e4.x : hsel == 1 ? e4.y : hsel == 2 ? e4.z : e4.w;
        float a = expf(lrelu(el_s + er_s) - mx_s) * r_s;
        const float4* fr = (const float4*)(fb + (size_t)s * HD_ + lane * 8);
        float4 f0 = fr[0], f1 = fr[1];
        accA.x += a * f0.x; accA.y += a * f0.y; accA.z += a * f0.z; accA.w += a * f0.w;
        accB.x += a * f1.x; accB.y += a * f1.y; accB.z += a * f1.z; accB.w += a * f1.w;
    }

    const float* brow = bias + m * HD_ + lane * 8;
    float4 b0 = *(const float4*)brow;
    float4 b1 = *(const float4*)(brow + 4);
    accA.x += b0.x; accA.y += b0.y; accA.z += b0.z; accA.w += b0.w;
    accB.x += b1.x; accB.y += b1.y; accB.z += b1.z; accB.w += b1.w;
    float* zr = g_z + (size_t)warp * HD_ + lane * 8;
    *(float4*)zr = accA;
    *(float4*)(zr + 4) = accB;
}

// ---------------- semantic attention: w = hid . W2, mean over nodes ----------------
__global__ void wdot_kernel(const float* __restrict__ W2) {
    int g = blockIdx.x * blockDim.x + threadIdx.x;
    int warp = g >> 5, lane = g & 31;
    if (warp >= M_ * N_) return;
    const float* hr = g_hid + (size_t)warp * HID_;
    float p = 0.f;
#pragma unroll
    for (int k = 0; k < 4; k++) {
        int j = lane + (k << 5);
        p += hr[j] * W2[j];
    }
#pragma unroll
    for (int s = 16; s > 0; s >>= 1)
        p += __shfl_xor_sync(0xffffffffu, p, s);
    if (lane == 0) atomicAdd(&g_wsum[warp / N_], p);
}

__global__ void beta_kernel() {
    if (threadIdx.x == 0 && blockIdx.x == 0) {
        float w0 = g_wsum[0] / (float)N_;
        float w1 = g_wsum[1] / (float)N_;
        float w2 = g_wsum[2] / (float)N_;
        float mx = fmaxf(w0, fmaxf(w1, w2));
        float e0 = expf(w0 - mx), e1 = expf(w1 - mx), e2 = expf(w2 - mx);
        float s = e0 + e1 + e2;
        g_beta[0] = e0 / s; g_beta[1] = e1 / s; g_beta[2] = e2 / s;
    }
}

// ---------------- final mix: out = sum_m beta[m] * z[m] ----------------
__global__ void final_kernel(float* __restrict__ out) {
    int i = blockIdx.x * blockDim.x + threadIdx.x;
    constexpr int S = N_ * HD_ / 4;
    if (i >= S) return;
    float b0 = g_beta[0], b1 = g_beta[1], b2 = g_beta[2];
    const float4* z = (const float4*)g_z;
    float4 v0 = z[i], v1 = z[i + S], v2 = z[i + 2 * S];
    float4 r;
    r.x = b0 * v0.x + b1 * v1.x + b2 * v2.x;
    r.y = b0 * v0.y + b1 * v1.y + b2 * v2.y;
    r.z = b0 * v0.z + b1 * v1.z + b2 * v2.z;
    r.w = b0 * v0.w + b1 * v1.w + b2 * v2.w;
    ((float4*)out)[i] = r;
}

// ---------------- launch ----------------
extern "C" void kernel_launch(void* const* d_in, const int* in_sizes, int n_in,
                              void* d_out, int out_size) {
    const float* h      = (const float*)d_in[0];
    const int*   src    = (const int*)d_in[1];
    const int*   dst    = (const int*)d_in[2];
    const float* W      = (const float*)d_in[3];
    const float* attn_l = (const float*)d_in[4];
    const float* attn_r = (const float*)d_in[5];
    const float* bias   = (const float*)d_in[6];
    const float* sem_W1 = (const float*)d_in[7];
    const float* sem_b1 = (const float*)d_in[8];
    const float* sem_W2 = (const float*)d_in[9];
    float* out = (float*)d_out;

    float *feat, *z, *hid;
    cudaGetSymbolAddress((void**)&feat, g_feat);
    cudaGetSymbolAddress((void**)&z, g_z);
    cudaGetSymbolAddress((void**)&hid, g_hid);

    init_kernel<<<(M_ * N_ + 255) / 256, 256>>>();

    // GEMM1: feat[m] = h @ W[m]  (A shared across batch)
    gemm_kernel<<<dim3((N_ + 63) / 64, HD_ / 64, M_), 256>>>(
        h, W, feat, N_, IN_, HD_,
        0L, (long)IN_ * HD_, (long)N_ * HD_, nullptr, 0);

    elr_kernel<<<(M_ * N_ * 32 + 255) / 256, 256>>>(attn_l, attn_r);

    hist_kernel<<<(M_ * E_ + 255) / 256, 256>>>(dst);
    scan_kernel<<<M_, 256>>>();
    scatter_kernel<<<(M_ * E_ + 255) / 256, 256>>>(src, dst);

    agg_kernel<<<(M_ * N_ * 32 + 255) / 256, 256>>>(bias);

    // GEMM2: hid = tanh(z @ sem_W1 + sem_b1), rows = M*N
    gemm_kernel<<<dim3((M_ * N_ + 63) / 64, HID_ / 64, 1), 256>>>(
        z, sem_W1, hid, M_ * N_, HD_, HID_,
        0L, 0L, 0L, sem_b1, 1);

    wdot_kernel<<<(M_ * N_ * 32 + 255) / 256, 256>>>(sem_W2);
    beta_kernel<<<1, 32>>>();
    final_kernel<<<(N_ * HD_ / 4 + 255) / 256, 256>>>(out);
}